// round 1
// baseline (speedup 1.0000x reference)
#include <cuda_runtime.h>
#include <math.h>

#define BROWS 8192
#define DDIM  512
#define KDIM  4096
#define LSTEPS 16
#define BM 64
#define BN 128
#define BKD 32
#define NBLK (BROWS / BM)
#define NTHREADS 256

// Residual working buffer (static device allocation — allowed by harness rules)
__device__ float g_resid[BROWS * DDIM];

__device__ __forceinline__ unsigned long long dup_f(float a) {
    unsigned long long r;
    asm("mov.b64 %0, {%1, %1};" : "=l"(r) : "f"(a));
    return r;
}
__device__ __forceinline__ void ffma2(unsigned long long &c, unsigned long long a, unsigned long long b) {
    asm("fma.rn.f32x2 %0, %1, %2, %0;" : "+l"(c) : "l"(a), "l"(b));
}
__device__ __forceinline__ float2 unpk(unsigned long long c) {
    float2 f;
    asm("mov.b64 {%0, %1}, %2;" : "=f"(f.x), "=f"(f.y) : "l"(c));
    return f;
}

__global__ __launch_bounds__(NTHREADS, 1)
void lex_step_kernel(const float* __restrict__ targets,
                     const float* __restrict__ codebook,
                     float* __restrict__ out,
                     int step, float decay)
{
    __shared__ float  As[BKD][BM + 4];          // [32][68] transposed A tile
    __shared__ float2 Bs[BKD][BN / 2 + 1];      // [32][65] pairs (n, n+64)
    __shared__ float  s_rn[BM];
    __shared__ float  s_tn[BM];
    __shared__ float  s_cabs[BM][17];
    __shared__ int    s_csig[BM][17];
    __shared__ float  s_coef[BM];
    __shared__ int    s_kidx[BM];

    const int tid = threadIdx.x;
    const int tm = tid >> 4;     // 0..15, row group (4 rows each)
    const int tn = tid & 15;     // 0..15, column group
    const int rowbase = blockIdx.x * BM;
    const float* src = (step == 0) ? targets : g_resid;

    // ---- per-row norms (residual + target), needed only for "active" ----
    {
        int m = tid >> 2, part = tid & 3;
        const float* rp = src     + (size_t)(rowbase + m) * DDIM + part * 128;
        const float* tp = targets + (size_t)(rowbase + m) * DDIM + part * 128;
        float sr = 0.f, st = 0.f;
        #pragma unroll
        for (int d = 0; d < 128; d += 4) {
            float4 r4 = *(const float4*)(rp + d);
            sr += r4.x * r4.x + r4.y * r4.y + r4.z * r4.z + r4.w * r4.w;
            float4 t4 = *(const float4*)(tp + d);
            st += t4.x * t4.x + t4.y * t4.y + t4.z * t4.z + t4.w * t4.w;
        }
        sr += __shfl_xor_sync(0xffffffffu, sr, 1);
        sr += __shfl_xor_sync(0xffffffffu, sr, 2);
        st += __shfl_xor_sync(0xffffffffu, st, 1);
        st += __shfl_xor_sync(0xffffffffu, st, 2);
        if (part == 0) { s_rn[m] = sqrtf(sr); s_tn[m] = sqrtf(st); }
    }

    // ---- running argmax state (per thread: 4 rows) ----
    float bestA[4]; int bestK[4]; int bestS[4];
    #pragma unroll
    for (int i = 0; i < 4; ++i) { bestA[i] = -1.f; bestK[i] = 1 << 30; bestS[i] = 0; }

    // ---- GEMM over K tiles of 128 columns ----
    for (int kt = 0; kt < KDIM; kt += BN) {
        unsigned long long acc[4][4];
        #pragma unroll
        for (int i = 0; i < 4; ++i)
            #pragma unroll
            for (int j = 0; j < 4; ++j) acc[i][j] = 0ull;

        #pragma unroll 1
        for (int dt = 0; dt < DDIM; dt += BKD) {
            __syncthreads();
            // stage A: 64 rows x 32 d  (512 float4 loads, coalesced)
            #pragma unroll
            for (int i = 0; i < 2; ++i) {
                int idx = i * NTHREADS + tid;          // 0..511
                int m = idx >> 3, d4 = idx & 7;
                float4 v = *(const float4*)(src + (size_t)(rowbase + m) * DDIM + dt + d4 * 4);
                As[d4 * 4 + 0][m] = v.x;
                As[d4 * 4 + 1][m] = v.y;
                As[d4 * 4 + 2][m] = v.z;
                As[d4 * 4 + 3][m] = v.w;
            }
            // stage B: 128 cols x 32 d (1024 float4 loads, coalesced)
            #pragma unroll
            for (int i = 0; i < 4; ++i) {
                int idx = i * NTHREADS + tid;          // 0..1023
                int n = idx >> 3, d4 = idx & 7;
                float4 v = *(const float4*)(codebook + (size_t)(kt + n) * DDIM + dt + d4 * 4);
                int p = n & 63, c = n >> 6;
                ((float*)&Bs[d4 * 4 + 0][p])[c] = v.x;
                ((float*)&Bs[d4 * 4 + 1][p])[c] = v.y;
                ((float*)&Bs[d4 * 4 + 2][p])[c] = v.z;
                ((float*)&Bs[d4 * 4 + 3][p])[c] = v.w;
            }
            __syncthreads();
            // inner product: 4m x 4 f32x2-pairs per thread, packed FP32 FMA
            #pragma unroll 8
            for (int d = 0; d < BKD; ++d) {
                float4 a4 = *(const float4*)&As[d][tm * 4];
                unsigned long long a0 = dup_f(a4.x);
                unsigned long long a1 = dup_f(a4.y);
                unsigned long long a2 = dup_f(a4.z);
                unsigned long long a3 = dup_f(a4.w);
                #pragma unroll
                for (int j = 0; j < 4; ++j) {
                    float2 b = Bs[d][tn + 16 * j];
                    unsigned long long bb;
                    asm("mov.b64 %0, {%1, %2};" : "=l"(bb) : "f"(b.x), "f"(b.y));
                    ffma2(acc[0][j], a0, bb);
                    ffma2(acc[1][j], a1, bb);
                    ffma2(acc[2][j], a2, bb);
                    ffma2(acc[3][j], a3, bb);
                }
            }
        }
        // fold scores of this K-tile into the running per-row argmax
        #pragma unroll
        for (int i = 0; i < 4; ++i) {
            #pragma unroll
            for (int j = 0; j < 4; ++j) {
                float2 v = unpk(acc[i][j]);
                int k0 = kt + tn + 16 * j;
                int k1 = k0 + 64;
                float a0 = fabsf(v.x);
                float a1 = fabsf(v.y);
                if (a0 > bestA[i] || (a0 == bestA[i] && k0 < bestK[i])) {
                    bestA[i] = a0; bestK[i] = k0; bestS[i] = (v.x >= 0.f) ? k0 : -(k0 + 1);
                }
                if (a1 > bestA[i] || (a1 == bestA[i] && k1 < bestK[i])) {
                    bestA[i] = a1; bestK[i] = k1; bestS[i] = (v.y >= 0.f) ? k1 : -(k1 + 1);
                }
            }
        }
    }

    // ---- cross-thread argmax reduce (16 candidates per row) ----
    #pragma unroll
    for (int i = 0; i < 4; ++i) {
        s_cabs[tm * 4 + i][tn] = bestA[i];
        s_csig[tm * 4 + i][tn] = bestS[i];
    }
    __syncthreads();

    if (tid < BM) {
        int m = tid;
        float bA = -1.f; int bK = 1 << 30; int bS = 0;
        #pragma unroll
        for (int t = 0; t < 16; ++t) {
            int sg = s_csig[m][t];
            int k = (sg >= 0) ? sg : (-sg - 1);
            float a = s_cabs[m][t];
            if (a > bA || (a == bA && k < bK)) { bA = a; bK = k; bS = sg; }
        }
        bool active = (s_rn[m] >= 0.01f) && (s_tn[m] >= 1e-8f);
        s_coef[m] = active ? ((bS >= 0) ? decay : -decay) : 0.f;
        s_kidx[m] = bK;
        int row = rowbase + m;
        out[(size_t)row * LSTEPS + step] = active ? (float)bS : 0.f;
        out[(size_t)BROWS * LSTEPS + (size_t)row * LSTEPS + step] = active ? 1.f : 0.f;
    }
    __syncthreads();

    // ---- residual update: r -= coef * codebook[k]  (coef==0 when inactive) ----
    const bool last = (step == LSTEPS - 1);
    float* resout = out + 2 * (size_t)BROWS * LSTEPS;
    #pragma unroll 1
    for (int i = 0; i < 32; ++i) {
        int idx = i * NTHREADS + tid;   // float4 index, 8192 total per block
        int m = idx >> 7, d4 = idx & 127;
        int row = rowbase + m;
        float coef = s_coef[m];
        const float4 r4 = *(const float4*)(src + (size_t)row * DDIM + d4 * 4);
        const float4 c4 = *(const float4*)(codebook + (size_t)s_kidx[m] * DDIM + d4 * 4);
        float4 o;
        o.x = r4.x - coef * c4.x;
        o.y = r4.y - coef * c4.y;
        o.z = r4.z - coef * c4.z;
        o.w = r4.w - coef * c4.w;
        *(float4*)(g_resid + (size_t)row * DDIM + d4 * 4) = o;
        if (last) *(float4*)(resout + (size_t)row * DDIM + d4 * 4) = o;
    }
}

extern "C" void kernel_launch(void* const* d_in, const int* in_sizes, int n_in,
                              void* d_out, int out_size) {
    (void)n_in; (void)out_size;
    const float* targets;
    const float* codebook;
    if (in_sizes[0] == BROWS * DDIM) {
        targets  = (const float*)d_in[0];
        codebook = (const float*)d_in[1];
    } else {
        targets  = (const float*)d_in[1];
        codebook = (const float*)d_in[0];
    }
    float* out = (float*)d_out;
    for (int s = 0; s < LSTEPS; ++s) {
        float decay = powf(0.95f, (float)(s + 1));
        lex_step_kernel<<<NBLK, NTHREADS>>>(targets, codebook, out, s, decay);
    }
}

// round 2
// speedup vs baseline: 1.0808x; 1.0808x over previous
#include <cuda_runtime.h>
#include <math.h>

#define BROWS 8192
#define DDIM  512
#define KDIM  4096
#define LSTEPS 16
#define BM 64
#define BN 128
#define BKD 64
#define NBLK (BROWS / BM)
#define NTHREADS 256
#define DPAD 68                       // A smem row stride (floats), 16B-aligned
#define BSTRIDE 65                    // B smem row stride (float2)
#define NCHUNK ((KDIM / BN) * (DDIM / BKD))   // 256
#define SMEM_DYN_BYTES (DDIM * DPAD * 4 + 2 * BKD * BSTRIDE * 8)

__device__ float g_resid[BROWS * DDIM];
__device__ float g_tnorm[BROWS];

__device__ __forceinline__ unsigned long long dup_f(float a) {
    unsigned long long r;
    asm("mov.b64 %0, {%1, %1};" : "=l"(r) : "f"(a));
    return r;
}
__device__ __forceinline__ void ffma2(unsigned long long &c, unsigned long long a, unsigned long long b) {
    asm("fma.rn.f32x2 %0, %1, %2, %0;" : "+l"(c) : "l"(a), "l"(b));
}
__device__ __forceinline__ float2 unpk(unsigned long long c) {
    float2 f;
    asm("mov.b64 {%0, %1}, %2;" : "=f"(f.x), "=f"(f.y) : "l"(c));
    return f;
}

// Load one B chunk (BN cols x BKD d) into registers.
// Mapping: pg = tid>>4 handles rows {pg*4+i, pg*4+i+64}, d4 = tid&15 one float4 of d.
__device__ __forceinline__ void ldg_chunk(const float* __restrict__ codebook,
                                          int c, int pg, int d4, float4* st) {
    int kb = (c >> 3) * BN;
    int db = (c & 7) * BKD;
    const float* gb = codebook + (size_t)(kb + pg * 4) * DDIM + db + d4 * 4;
    #pragma unroll
    for (int i = 0; i < 4; ++i) {
        st[i]     = *(const float4*)(gb + (size_t)i * DDIM);
        st[4 + i] = *(const float4*)(gb + (size_t)(64 + i) * DDIM);
    }
}

__device__ __forceinline__ void sts_chunk(float2* __restrict__ bsb,
                                          int pg, int d4, const float4* st) {
    #pragma unroll
    for (int i = 0; i < 4; ++i) {
        int p = pg * 4 + i;
        const float* lo = (const float*)&st[i];
        const float* hi = (const float*)&st[4 + i];
        #pragma unroll
        for (int k = 0; k < 4; ++k) {
            bsb[(size_t)(d4 * 4 + k) * BSTRIDE + p] = make_float2(lo[k], hi[k]);
        }
    }
}

__global__ __launch_bounds__(NTHREADS, 1)
void lex_step_kernel(const float* __restrict__ targets,
                     const float* __restrict__ codebook,
                     float* __restrict__ out,
                     int step, float decay)
{
    extern __shared__ float dynsmem[];
    float*  As = dynsmem;                                 // [512][DPAD]
    float2* Bs = (float2*)(dynsmem + DDIM * DPAD);        // 2 x [BKD][BSTRIDE]

    __shared__ float s_pr[NTHREADS];
    __shared__ float s_cabs[BM][17];
    __shared__ int   s_csig[BM][17];
    __shared__ float s_coef[BM];
    __shared__ int   s_kidx[BM];

    const int tid = threadIdx.x;
    const int tm = tid >> 4;      // 0..15 (4 rows each)
    const int tn = tid & 15;      // 0..15
    const int rowbase = blockIdx.x * BM;
    const float* src = (step == 0) ? targets : g_resid;

    const int pg = tid >> 4;      // B staging row group
    const int d4 = tid & 15;      // B staging d-float4

    // ---- prefetch first B chunk ----
    float4 stage[8];
    ldg_chunk(codebook, 0, pg, d4, stage);

    // ---- stage A (transposed) once; fuse residual-norm accumulation ----
    {
        int m = tid & 63;
        int q = tid >> 6;                              // 0..3
        const float* srow = src + (size_t)(rowbase + m) * DDIM + q * 128;
        float sr = 0.f;
        #pragma unroll 8
        for (int i = 0; i < 32; ++i) {
            float4 v = *(const float4*)(srow + i * 4);
            sr += v.x * v.x + v.y * v.y + v.z * v.z + v.w * v.w;
            int d = q * 128 + i * 4;
            As[(size_t)(d + 0) * DPAD + m] = v.x;
            As[(size_t)(d + 1) * DPAD + m] = v.y;
            As[(size_t)(d + 2) * DPAD + m] = v.z;
            As[(size_t)(d + 3) * DPAD + m] = v.w;
        }
        s_pr[tid] = sr;
    }

    // ---- running argmax state ----
    float bestA[4]; int bestK[4]; int bestS[4];
    #pragma unroll
    for (int i = 0; i < 4; ++i) { bestA[i] = -1.f; bestK[i] = 1 << 30; bestS[i] = 0; }

    __syncthreads();   // As + s_pr ready

    // norms (uses s_pr; does not touch As/Bs)
    float rn_ = 0.f, tn_ = 0.f;
    if (tid < BM) {
        float s = s_pr[tid] + s_pr[tid + 64] + s_pr[tid + 128] + s_pr[tid + 192];
        rn_ = sqrtf(s);
        if (step == 0) { g_tnorm[rowbase + tid] = rn_; tn_ = rn_; }
        else           { tn_ = g_tnorm[rowbase + tid]; }
    }

    // ---- main loop: 32 K-tiles x 8 d-chunks, B double-buffered ----
    for (int kt = 0; kt < KDIM / BN; ++kt) {
        unsigned long long acc[4][4];
        #pragma unroll
        for (int i = 0; i < 4; ++i)
            #pragma unroll
            for (int j = 0; j < 4; ++j) acc[i][j] = 0ull;

        #pragma unroll 1
        for (int dt = 0; dt < DDIM / BKD; ++dt) {
            const int c = kt * 8 + dt;
            float2* bsb = Bs + (size_t)(c & 1) * (BKD * BSTRIDE);
            sts_chunk(bsb, pg, d4, stage);
            __syncthreads();
            int cn = (c + 1 < NCHUNK) ? (c + 1) : (NCHUNK - 1);
            ldg_chunk(codebook, cn, pg, d4, stage);

            const float* arow = As + (size_t)(dt * BKD) * DPAD + tm * 4;
            #pragma unroll 4
            for (int dd = 0; dd < BKD; ++dd) {
                float4 a4 = *(const float4*)(arow + (size_t)dd * DPAD);
                unsigned long long a0 = dup_f(a4.x);
                unsigned long long a1 = dup_f(a4.y);
                unsigned long long a2 = dup_f(a4.z);
                unsigned long long a3 = dup_f(a4.w);
                const float2* bp = bsb + (size_t)dd * BSTRIDE + tn;
                #pragma unroll
                for (int j = 0; j < 4; ++j) {
                    unsigned long long bb = *(const unsigned long long*)(bp + 16 * j);
                    ffma2(acc[0][j], a0, bb);
                    ffma2(acc[1][j], a1, bb);
                    ffma2(acc[2][j], a2, bb);
                    ffma2(acc[3][j], a3, bb);
                }
            }
            __syncthreads();   // protect bsb before it is overwritten 2 chunks later
        }

        // fold this K-tile's scores into running argmax
        const int ktb = kt * BN;
        #pragma unroll
        for (int i = 0; i < 4; ++i) {
            #pragma unroll
            for (int j = 0; j < 4; ++j) {
                float2 v = unpk(acc[i][j]);
                int k0 = ktb + tn + 16 * j;
                int k1 = k0 + 64;
                float a0 = fabsf(v.x);
                float a1 = fabsf(v.y);
                if (a0 > bestA[i] || (a0 == bestA[i] && k0 < bestK[i])) {
                    bestA[i] = a0; bestK[i] = k0; bestS[i] = (v.x >= 0.f) ? k0 : -(k0 + 1);
                }
                if (a1 > bestA[i] || (a1 == bestA[i] && k1 < bestK[i])) {
                    bestA[i] = a1; bestK[i] = k1; bestS[i] = (v.y >= 0.f) ? k1 : -(k1 + 1);
                }
            }
        }
    }

    // ---- cross-thread argmax reduce ----
    #pragma unroll
    for (int i = 0; i < 4; ++i) {
        s_cabs[tm * 4 + i][tn] = bestA[i];
        s_csig[tm * 4 + i][tn] = bestS[i];
    }
    __syncthreads();

    if (tid < BM) {
        int m = tid;
        float bA = -1.f; int bK = 1 << 30; int bS = 0;
        #pragma unroll
        for (int t = 0; t < 16; ++t) {
            int sg = s_csig[m][t];
            int k = (sg >= 0) ? sg : (-sg - 1);
            float a = s_cabs[m][t];
            if (a > bA || (a == bA && k < bK)) { bA = a; bK = k; bS = sg; }
        }
        bool active = (rn_ >= 0.01f) && (tn_ >= 1e-8f);
        s_coef[m] = active ? ((bS >= 0) ? decay : -decay) : 0.f;
        s_kidx[m] = bK;
        int row = rowbase + m;
        out[(size_t)row * LSTEPS + step] = active ? (float)bS : 0.f;
        out[(size_t)BROWS * LSTEPS + (size_t)row * LSTEPS + step] = active ? 1.f : 0.f;
    }
    __syncthreads();

    // ---- residual update: r -= coef * codebook[k] ----
    const bool last = (step == LSTEPS - 1);
    float* resout = out + 2 * (size_t)BROWS * LSTEPS;
    #pragma unroll 1
    for (int i = 0; i < 32; ++i) {
        int idx = i * NTHREADS + tid;   // float4 index, 8192 per block
        int m = idx >> 7, dq = idx & 127;
        int row = rowbase + m;
        float coef = s_coef[m];
        const float4 r4 = *(const float4*)(src + (size_t)row * DDIM + dq * 4);
        const float4 c4 = *(const float4*)(codebook + (size_t)s_kidx[m] * DDIM + dq * 4);
        float4 o;
        o.x = r4.x - coef * c4.x;
        o.y = r4.y - coef * c4.y;
        o.z = r4.z - coef * c4.z;
        o.w = r4.w - coef * c4.w;
        *(float4*)(g_resid + (size_t)row * DDIM + dq * 4) = o;
        if (last) *(float4*)(resout + (size_t)row * DDIM + dq * 4) = o;
    }
}

extern "C" void kernel_launch(void* const* d_in, const int* in_sizes, int n_in,
                              void* d_out, int out_size) {
    (void)n_in; (void)out_size;
    const float* targets;
    const float* codebook;
    if (in_sizes[0] == BROWS * DDIM) {
        targets  = (const float*)d_in[0];
        codebook = (const float*)d_in[1];
    } else {
        targets  = (const float*)d_in[1];
        codebook = (const float*)d_in[0];
    }
    cudaFuncSetAttribute(lex_step_kernel,
                         cudaFuncAttributeMaxDynamicSharedMemorySize, SMEM_DYN_BYTES);
    float* out = (float*)d_out;
    for (int s = 0; s < LSTEPS; ++s) {
        float decay = powf(0.95f, (float)(s + 1));
        lex_step_kernel<<<NBLK, NTHREADS, SMEM_DYN_BYTES>>>(targets, codebook, out, s, decay);
    }
}

// round 5
// speedup vs baseline: 1.5572x; 1.4408x over previous
#include <cuda_runtime.h>
#include <math.h>
#include <stdint.h>

#define BROWS 8192
#define DDIM  512
#define KDIM  4096
#define LSTEPS 16

#define GM 128
#define GN 256
#define NCB (KDIM / GN)        // 16 column blocks
#define NC 48                  // K' chunks: 3 passes x 16 chunks of 32
#define GTHREADS 256

#define ASTRIDE 36             // floats per smem row (32 data + 4 pad)
#define ABUF_FLOATS (GM * ASTRIDE)
#define BBUF_FLOATS (GN * ASTRIDE)
#define BUF_FLOATS (ABUF_FLOATS + BBUF_FLOATS)
#define SMEM_DYN (2 * BUF_FLOATS * 4)

// ---------------- device state ----------------
__device__ __align__(128) float g_resid[BROWS * DDIM];
__device__ __align__(128) float g_A2[BROWS * 1024];   // [row][0:512)=hi, [512:1024)=lo
__device__ __align__(128) float g_B2[KDIM * 1024];
__device__ float g_rnorm[BROWS];
__device__ float g_tnorm[BROWS];
__device__ float g_pA[2 * NCB * BROWS];
__device__ int   g_pS[2 * NCB * BROWS];

// ---------------- helpers ----------------
__device__ __forceinline__ float tf32_rna(float a) {
    float r;
    asm("cvt.rna.tf32.f32 %0, %1;" : "=f"(r) : "f"(a));
    return r;
}
__device__ __forceinline__ uint32_t smem_u32(const void* p) {
    uint32_t a;
    asm("{ .reg .u64 t; cvta.to.shared.u64 t, %1; cvt.u32.u64 %0, t; }" : "=r"(a) : "l"(p));
    return a;
}
__device__ __forceinline__ void cpasync16(uint32_t dst, const void* src) {
    asm volatile("cp.async.cg.shared.global [%0], [%1], 16;" :: "r"(dst), "l"(src));
}
#define CP_COMMIT() asm volatile("cp.async.commit_group;" ::: "memory")

__device__ __forceinline__ void mma_tf32(float* d, const uint32_t* a, const uint32_t* b) {
    asm volatile(
        "mma.sync.aligned.m16n8k8.row.col.f32.tf32.tf32.f32 "
        "{%0,%1,%2,%3}, {%4,%5,%6,%7}, {%8,%9}, {%0,%1,%2,%3};"
        : "+f"(d[0]), "+f"(d[1]), "+f"(d[2]), "+f"(d[3])
        : "r"(a[0]), "r"(a[1]), "r"(a[2]), "r"(a[3]), "r"(b[0]), "r"(b[1]));
}

__device__ __forceinline__ void split4(float4 v, float4& h, float4& l) {
    h.x = tf32_rna(v.x); l.x = tf32_rna(v.x - h.x);
    h.y = tf32_rna(v.y); l.y = tf32_rna(v.y - h.y);
    h.z = tf32_rna(v.z); l.z = tf32_rna(v.z - h.z);
    h.w = tf32_rna(v.w); l.w = tf32_rna(v.w - h.w);
}

// ---------------- prep: split inputs into tf32 hi/lo, norms ----------------
__global__ __launch_bounds__(256)
void lex_prep(const float* __restrict__ targets, const float* __restrict__ codebook) {
    const int tid = threadIdx.x;
    const int m = tid >> 2, q = tid & 3;
    if (blockIdx.x < 128) {
        int row = blockIdx.x * 64 + m;
        const float* src = targets + (size_t)row * DDIM + q * 128;
        float* dsthi = g_A2 + (size_t)row * 1024 + q * 128;
        float sum = 0.f;
        #pragma unroll 8
        for (int i = 0; i < 32; ++i) {
            float4 v = *(const float4*)(src + i * 4);
            sum += v.x * v.x + v.y * v.y + v.z * v.z + v.w * v.w;
            float4 h, l;
            split4(v, h, l);
            *(float4*)(dsthi + i * 4) = h;
            *(float4*)(dsthi + 512 + i * 4) = l;
        }
        sum += __shfl_xor_sync(0xffffffffu, sum, 1);
        sum += __shfl_xor_sync(0xffffffffu, sum, 2);
        if (q == 0) { float n = sqrtf(sum); g_rnorm[row] = n; g_tnorm[row] = n; }
    } else {
        int row = (blockIdx.x - 128) * 64 + m;
        const float* src = codebook + (size_t)row * DDIM + q * 128;
        float* dsthi = g_B2 + (size_t)row * 1024 + q * 128;
        #pragma unroll 8
        for (int i = 0; i < 32; ++i) {
            float4 v = *(const float4*)(src + i * 4);
            float4 h, l;
            split4(v, h, l);
            *(float4*)(dsthi + i * 4) = h;
            *(float4*)(dsthi + 512 + i * 4) = l;
        }
    }
}

// ---------------- GEMM + top-2 candidates (per step) ----------------
__global__ __launch_bounds__(GTHREADS, 1)
void lex_gemm() {
    extern __shared__ float dsm[];
    __shared__ float s_cabs[2][GM][17];
    __shared__ int   s_csig[2][GM][17];

    const int tid = threadIdx.x;
    const int wid = tid >> 5;
    const int lane = tid & 31;
    const int tg = lane >> 2;
    const int tq = lane & 3;
    const int wm = wid >> 2;
    const int wn = wid & 3;
    const int rowblock = blockIdx.x >> 4;
    const int cb = blockIdx.x & 15;
    const int rowbase = rowblock * GM;
    const int colbase = cb * GN;
    const uint32_t sbase = smem_u32(dsm);

    // pass0: hi*hi  pass1: lo*hi  pass2: hi*lo
    auto issue = [&](int c) {
        const int pass = c >> 4, cc = c & 15;
        const int dA = ((pass == 1) ? 512 : 0) + cc * 32;
        const int dB = ((pass == 2) ? 512 : 0) + cc * 32;
        const uint32_t bufb = sbase + (uint32_t)(c & 1) * (BUF_FLOATS * 4);
        #pragma unroll
        for (int i = 0; i < 4; ++i) {
            int idx = tid + i * GTHREADS;
            int m = idx >> 3, c16 = idx & 7;
            cpasync16(bufb + (uint32_t)(m * ASTRIDE * 4 + c16 * 16),
                      g_A2 + (size_t)(rowbase + m) * 1024 + dA + c16 * 4);
        }
        const uint32_t bufbB = bufb + ABUF_FLOATS * 4;
        #pragma unroll
        for (int i = 0; i < 8; ++i) {
            int idx = tid + i * GTHREADS;
            int n = idx >> 3, c16 = idx & 7;
            cpasync16(bufbB + (uint32_t)(n * ASTRIDE * 4 + c16 * 16),
                      g_B2 + (size_t)(colbase + n) * 1024 + dB + c16 * 4);
        }
        CP_COMMIT();
    };

    float acc[4][8][4];
    #pragma unroll
    for (int i = 0; i < 4; ++i)
        #pragma unroll
        for (int j = 0; j < 8; ++j)
            #pragma unroll
            for (int r = 0; r < 4; ++r) acc[i][j][r] = 0.f;

    issue(0);

    for (int c = 0; c < NC; ++c) {
        if (c + 1 < NC) {
            issue(c + 1);
            asm volatile("cp.async.wait_group 1;" ::: "memory");
        } else {
            asm volatile("cp.async.wait_group 0;" ::: "memory");
        }
        __syncthreads();

        const float* As = dsm + (size_t)(c & 1) * BUF_FLOATS;
        const float* Bs = As + ABUF_FLOATS;

        #pragma unroll
        for (int s = 0; s < 4; ++s) {
            uint32_t af[4][4];
            #pragma unroll
            for (int i = 0; i < 4; ++i) {
                int r = wm * 64 + i * 16 + tg;
                const float* p0 = As + r * ASTRIDE + s * 8;
                const float* p1 = As + (r + 8) * ASTRIDE + s * 8;
                af[i][0] = __float_as_uint(p0[tq]);
                af[i][1] = __float_as_uint(p1[tq]);
                af[i][2] = __float_as_uint(p0[tq + 4]);
                af[i][3] = __float_as_uint(p1[tq + 4]);
            }
            uint32_t bf[8][2];
            #pragma unroll
            for (int j = 0; j < 8; ++j) {
                int n = wn * 64 + j * 8 + tg;
                const float* p = Bs + n * ASTRIDE + s * 8;
                bf[j][0] = __float_as_uint(p[tq]);
                bf[j][1] = __float_as_uint(p[tq + 4]);
            }
            #pragma unroll
            for (int i = 0; i < 4; ++i)
                #pragma unroll
                for (int j = 0; j < 8; ++j)
                    mma_tf32(acc[i][j], af[i], bf[j]);
        }
        __syncthreads();
    }

    // ---- epilogue: per-row TOP-2 candidates ----
    #pragma unroll
    for (int i = 0; i < 4; ++i) {
        #pragma unroll
        for (int h = 0; h < 2; ++h) {
            float a1 = -1.f, a2 = -1.f;
            int s1 = 0, s2 = 0;
            #pragma unroll
            for (int j = 0; j < 8; ++j) {
                #pragma unroll
                for (int cc = 0; cc < 2; ++cc) {
                    float v = acc[i][j][h * 2 + cc];
                    float a = fabsf(v);
                    int k = colbase + wn * 64 + j * 8 + tq * 2 + cc;
                    int sg = (v >= 0.f) ? k : -(k + 1);
                    if (a > a1) { a2 = a1; s2 = s1; a1 = a; s1 = sg; }
                    else if (a > a2) { a2 = a; s2 = sg; }
                }
            }
            int rl = wm * 64 + i * 16 + tg + 8 * h;
            s_cabs[0][rl][wn * 4 + tq] = a1;
            s_csig[0][rl][wn * 4 + tq] = s1;
            s_cabs[1][rl][wn * 4 + tq] = a2;
            s_csig[1][rl][wn * 4 + tq] = s2;
        }
    }
    __syncthreads();

    if (tid < GM) {
        float A1 = -1.f, A2 = -1.f;
        int S1 = 0, S2 = 0, K1 = 1 << 30, K2 = 1 << 30;
        #pragma unroll
        for (int t = 0; t < 16; ++t) {
            #pragma unroll
            for (int slot = 0; slot < 2; ++slot) {
                float a = s_cabs[slot][tid][t];
                int sg = s_csig[slot][tid][t];
                int k = (sg >= 0) ? sg : (-sg - 1);
                if (a > A1 || (a == A1 && k < K1)) {
                    A2 = A1; S2 = S1; K2 = K1;
                    A1 = a; S1 = sg; K1 = k;
                } else if (a > A2 || (a == A2 && k < K2)) {
                    A2 = a; S2 = sg; K2 = k;
                }
            }
        }
        g_pA[(cb * 2 + 0) * BROWS + rowbase + tid] = A1;
        g_pS[(cb * 2 + 0) * BROWS + rowbase + tid] = S1;
        g_pA[(cb * 2 + 1) * BROWS + rowbase + tid] = A2;
        g_pS[(cb * 2 + 1) * BROWS + rowbase + tid] = S2;
    }
}

// ---------------- merge + exact fp32 rescore + residual update ----------------
__global__ __launch_bounds__(256)
void lex_update(const float* __restrict__ targets, const float* __restrict__ codebook,
                float* __restrict__ out, int step, float decay) {
    __shared__ int   s_kA[64], s_kB[64];
    __shared__ int   s_act[64];
    __shared__ float s_coef[64];
    __shared__ int   s_kidx[64];
    const int tid = threadIdx.x;
    const int rowbase = blockIdx.x * 64;
    const float* src = (step == 0) ? targets : g_resid;

    // phase 1: merge 32 tensor candidates -> global top-2 per row
    if (tid < 64) {
        int row = rowbase + tid;
        float A1 = -1.f, A2 = -1.f;
        int K1 = 0, K2 = 0, KK1 = 1 << 30, KK2 = 1 << 30;
        #pragma unroll
        for (int cbi = 0; cbi < NCB; ++cbi) {
            #pragma unroll
            for (int slot = 0; slot < 2; ++slot) {
                float a = g_pA[(cbi * 2 + slot) * BROWS + row];
                int sg = g_pS[(cbi * 2 + slot) * BROWS + row];
                int k = (sg >= 0) ? sg : (-sg - 1);
                if (a > A1 || (a == A1 && k < KK1)) {
                    A2 = A1; K2 = K1; KK2 = KK1;
                    A1 = a; K1 = k; KK1 = k;
                } else if (a > A2 || (a == A2 && k < KK2)) {
                    A2 = a; K2 = k; KK2 = k;
                }
            }
        }
        s_kA[tid] = K1;
        s_kB[tid] = K2;
        s_act[tid] = (g_rnorm[row] >= 0.01f) && (g_tnorm[row] >= 1e-8f);
    }
    __syncthreads();

    // phase 2: exact fp32 rescore of both candidates
    const int m = tid >> 2, q = tid & 3;
    const int row = rowbase + m;
    const int kA = s_kA[m], kB = s_kB[m];
    {
        const float* rp = src + (size_t)row * DDIM + q * 128;
        const float* cA = codebook + (size_t)kA * DDIM + q * 128;
        const float* cB = codebook + (size_t)kB * DDIM + q * 128;
        float dA = 0.f, dB = 0.f;
        #pragma unroll 8
        for (int i = 0; i < 32; ++i) {
            float4 r4 = *(const float4*)(rp + i * 4);
            float4 a4 = *(const float4*)(cA + i * 4);
            float4 b4 = *(const float4*)(cB + i * 4);
            dA += r4.x * a4.x + r4.y * a4.y + r4.z * a4.z + r4.w * a4.w;
            dB += r4.x * b4.x + r4.y * b4.y + r4.z * b4.z + r4.w * b4.w;
        }
        dA += __shfl_xor_sync(0xffffffffu, dA, 1);
        dA += __shfl_xor_sync(0xffffffffu, dA, 2);
        dB += __shfl_xor_sync(0xffffffffu, dB, 1);
        dB += __shfl_xor_sync(0xffffffffu, dB, 2);
        if (q == 0) {
            float aA = fabsf(dA), aB = fabsf(dB);
            bool useB = (aB > aA) || (aB == aA && kB < kA);
            int k = useB ? kB : kA;
            float v = useB ? dB : dA;
            int bS = (v >= 0.f) ? k : -(k + 1);
            bool active = s_act[m];
            s_coef[m] = active ? ((v >= 0.f) ? decay : -decay) : 0.f;
            s_kidx[m] = k;
            out[(size_t)row * LSTEPS + step] = active ? (float)bS : 0.f;
            out[(size_t)BROWS * LSTEPS + (size_t)row * LSTEPS + step] = active ? 1.f : 0.f;
        }
    }
    __syncthreads();

    // phase 3: residual update + re-split + rnorm
    const bool last = (step == LSTEPS - 1);
    float* resout = out + 2 * (size_t)BROWS * LSTEPS;
    const float coef = s_coef[m];
    const int k = s_kidx[m];
    const size_t base = (size_t)row * DDIM + q * 128;
    const size_t cbo = (size_t)k * DDIM + q * 128;
    float* dsthi = g_A2 + (size_t)row * 1024 + q * 128;
    float sum = 0.f;
    #pragma unroll 8
    for (int i = 0; i < 32; ++i) {
        float4 r4 = *(const float4*)(src + base + i * 4);
        float4 c4 = *(const float4*)(codebook + cbo + i * 4);
        float4 o;
        o.x = r4.x - coef * c4.x;
        o.y = r4.y - coef * c4.y;
        o.z = r4.z - coef * c4.z;
        o.w = r4.w - coef * c4.w;
        sum += o.x * o.x + o.y * o.y + o.z * o.z + o.w * o.w;
        *(float4*)(g_resid + base + i * 4) = o;
        float4 h, l;
        split4(o, h, l);
        *(float4*)(dsthi + i * 4) = h;
        *(float4*)(dsthi + 512 + i * 4) = l;
        if (last) *(float4*)(resout + base + i * 4) = o;
    }
    sum += __shfl_xor_sync(0xffffffffu, sum, 1);
    sum += __shfl_xor_sync(0xffffffffu, sum, 2);
    if (q == 0) g_rnorm[row] = sqrtf(sum);
}

extern "C" void kernel_launch(void* const* d_in, const int* in_sizes, int n_in,
                              void* d_out, int out_size) {
    (void)n_in; (void)out_size;
    const float* targets;
    const float* codebook;
    if (in_sizes[0] == BROWS * DDIM) {
        targets  = (const float*)d_in[0];
        codebook = (const float*)d_in[1];
    } else {
        targets  = (const float*)d_in[1];
        codebook = (const float*)d_in[0];
    }
    cudaFuncSetAttribute(lex_gemm, cudaFuncAttributeMaxDynamicSharedMemorySize, SMEM_DYN);
    float* out = (float*)d_out;

    lex_prep<<<192, 256>>>(targets, codebook);
    for (int s = 0; s < LSTEPS; ++s) {
        float decay = powf(0.95f, (float)(s + 1));
        lex_gemm<<<(BROWS / GM) * NCB, GTHREADS, SMEM_DYN>>>();
        lex_update<<<BROWS / 64, 256>>>(targets, codebook, out, s, decay);
    }
}

// round 6
// speedup vs baseline: 2.3737x; 1.5243x over previous
#include <cuda_runtime.h>
#include <cuda_bf16.h>
#include <math.h>
#include <stdint.h>

#define BROWS 8192
#define DDIM  512
#define KDIM  4096
#define LSTEPS 16

#define GM 128
#define GN 256
#define NCB (KDIM / GN)        // 16 column blocks
#define NC 48                  // 3 passes x 16 d-chunks (32 d each)
#define GTHREADS 256
#define STAGES 4

#define ROWB 80                            // smem bytes per row (64 data + 16 pad)
#define ABYTES (GM * ROWB)                 // 10240
#define BBYTES (GN * ROWB)                 // 20480
#define STAGEB (ABYTES + BBYTES)           // 30720
#define SMEM_DYN (STAGES * STAGEB)         // 122880

// ---------------- device state ----------------
__device__ __align__(128) float g_resid[BROWS * DDIM];
__device__ __align__(128) __nv_bfloat16 g_Abf[BROWS * 1024];  // [row][0:512)=hi,[512:1024)=lo
__device__ __align__(128) __nv_bfloat16 g_Bbf[KDIM * 1024];
__device__ float g_rnorm[BROWS];
__device__ float g_tnorm[BROWS];
__device__ float g_pA[4 * NCB * BROWS];
__device__ int   g_pS[4 * NCB * BROWS];

// ---------------- helpers ----------------
__device__ __forceinline__ uint32_t smem_u32(const void* p) {
    uint32_t a;
    asm("{ .reg .u64 t; cvta.to.shared.u64 t, %1; cvt.u32.u64 %0, t; }" : "=r"(a) : "l"(p));
    return a;
}
__device__ __forceinline__ void cpasync16(uint32_t dst, const void* src) {
    asm volatile("cp.async.cg.shared.global [%0], [%1], 16;" :: "r"(dst), "l"(src));
}
#define CP_COMMIT() asm volatile("cp.async.commit_group;" ::: "memory")

__device__ __forceinline__ void mma_bf16(float* d, const uint32_t* a, const uint32_t* b) {
    asm volatile(
        "mma.sync.aligned.m16n8k16.row.col.f32.bf16.bf16.f32 "
        "{%0,%1,%2,%3}, {%4,%5,%6,%7}, {%8,%9}, {%0,%1,%2,%3};"
        : "+f"(d[0]), "+f"(d[1]), "+f"(d[2]), "+f"(d[3])
        : "r"(a[0]), "r"(a[1]), "r"(a[2]), "r"(a[3]), "r"(b[0]), "r"(b[1]));
}

__device__ __forceinline__ void split_bf(float v, __nv_bfloat16& h, __nv_bfloat16& l) {
    h = __float2bfloat16(v);
    l = __float2bfloat16(v - __bfloat162float(h));
}

// ---------------- prep: split inputs into bf16 hi/lo, norms ----------------
__global__ __launch_bounds__(256)
void lex_prep(const float* __restrict__ targets, const float* __restrict__ codebook) {
    const int tid = threadIdx.x;
    const int m = tid >> 2, q = tid & 3;
    if (blockIdx.x < 128) {
        int row = blockIdx.x * 64 + m;
        const float* src = targets + (size_t)row * DDIM + q * 128;
        __nv_bfloat16* dst = g_Abf + (size_t)row * 1024 + q * 128;
        float sum = 0.f;
        #pragma unroll 8
        for (int i = 0; i < 128; ++i) {
            float v = src[i];
            sum += v * v;
            split_bf(v, dst[i], dst[512 + i]);
        }
        sum += __shfl_xor_sync(0xffffffffu, sum, 1);
        sum += __shfl_xor_sync(0xffffffffu, sum, 2);
        if (q == 0) { float n = sqrtf(sum); g_rnorm[row] = n; g_tnorm[row] = n; }
    } else {
        int row = (blockIdx.x - 128) * 64 + m;
        const float* src = codebook + (size_t)row * DDIM + q * 128;
        __nv_bfloat16* dst = g_Bbf + (size_t)row * 1024 + q * 128;
        #pragma unroll 8
        for (int i = 0; i < 128; ++i) {
            split_bf(src[i], dst[i], dst[512 + i]);
        }
    }
}

// ---------------- GEMM (bf16 triple) + top-4 candidates ----------------
__global__ __launch_bounds__(GTHREADS, 1)
void lex_gemm() {
    extern __shared__ char dsm[];
    __shared__ float s_cabs[2][GM][17];
    __shared__ int   s_csig[2][GM][17];

    const int tid = threadIdx.x;
    const int wid = tid >> 5;
    const int lane = tid & 31;
    const int tg = lane >> 2;
    const int tq = lane & 3;
    const int wm = wid >> 2;
    const int wn = wid & 3;
    const int rowblock = blockIdx.x >> 4;
    const int cb = blockIdx.x & 15;
    const int rowbase = rowblock * GM;
    const int colbase = cb * GN;
    const uint32_t sbase = smem_u32(dsm);

    // pass0: hi*hi  pass1: lo*hi  pass2: hi*lo
    auto issue = [&](int c) {
        const int pass = c >> 4, cc = c & 15;
        const int dA = ((pass == 1) ? 512 : 0) + cc * 32;
        const int dB = ((pass == 2) ? 512 : 0) + cc * 32;
        const uint32_t base = sbase + (uint32_t)(c & (STAGES - 1)) * STAGEB;
        #pragma unroll
        for (int i = 0; i < 2; ++i) {
            int idx = tid + i * GTHREADS;     // 0..511
            int r = idx >> 2, c16 = idx & 3;
            cpasync16(base + (uint32_t)(r * ROWB + c16 * 16),
                      g_Abf + (size_t)(rowbase + r) * 1024 + dA + c16 * 8);
        }
        #pragma unroll
        for (int i = 0; i < 4; ++i) {
            int idx = tid + i * GTHREADS;     // 0..1023
            int n = idx >> 2, c16 = idx & 3;
            cpasync16(base + ABYTES + (uint32_t)(n * ROWB + c16 * 16),
                      g_Bbf + (size_t)(colbase + n) * 1024 + dB + c16 * 8);
        }
        CP_COMMIT();
    };

    float acc[4][8][4];
    #pragma unroll
    for (int i = 0; i < 4; ++i)
        #pragma unroll
        for (int j = 0; j < 8; ++j)
            #pragma unroll
            for (int r = 0; r < 4; ++r) acc[i][j][r] = 0.f;

    issue(0); issue(1); issue(2);

    for (int c = 0; c < NC; ++c) {
        asm volatile("cp.async.wait_group 2;" ::: "memory");
        __syncthreads();
        if (c + 3 < NC) issue(c + 3);
        else CP_COMMIT();                       // keep group count uniform

        const char* As = dsm + (size_t)(c & (STAGES - 1)) * STAGEB;
        const char* Bs = As + ABYTES;

        #pragma unroll
        for (int ks = 0; ks < 2; ++ks) {
            const int koff = ks * 32;           // 16 bf16 = 32 bytes
            uint32_t af[4][4];
            #pragma unroll
            for (int i = 0; i < 4; ++i) {
                const char* p0 = As + (wm * 64 + i * 16 + tg) * ROWB + koff + tq * 4;
                af[i][0] = *(const uint32_t*)(p0);
                af[i][1] = *(const uint32_t*)(p0 + 8 * ROWB);
                af[i][2] = *(const uint32_t*)(p0 + 16);
                af[i][3] = *(const uint32_t*)(p0 + 8 * ROWB + 16);
            }
            uint32_t bf_[8][2];
            #pragma unroll
            for (int j = 0; j < 8; ++j) {
                const char* p = Bs + (wn * 64 + j * 8 + tg) * ROWB + koff + tq * 4;
                bf_[j][0] = *(const uint32_t*)(p);
                bf_[j][1] = *(const uint32_t*)(p + 16);
            }
            #pragma unroll
            for (int i = 0; i < 4; ++i)
                #pragma unroll
                for (int j = 0; j < 8; ++j)
                    mma_bf16(acc[i][j], af[i], bf_[j]);
        }
    }

    // ---- per-thread top-2 candidates per row-slot ----
    #pragma unroll
    for (int i = 0; i < 4; ++i) {
        #pragma unroll
        for (int h = 0; h < 2; ++h) {
            float a1 = -1.f, a2 = -1.f;
            int s1 = 0, s2 = 0;
            #pragma unroll
            for (int j = 0; j < 8; ++j) {
                #pragma unroll
                for (int cc = 0; cc < 2; ++cc) {
                    float v = acc[i][j][h * 2 + cc];
                    float a = fabsf(v);
                    int k = colbase + wn * 64 + j * 8 + tq * 2 + cc;
                    int sg = (v >= 0.f) ? k : -(k + 1);
                    if (a > a1) { a2 = a1; s2 = s1; a1 = a; s1 = sg; }
                    else if (a > a2) { a2 = a; s2 = sg; }
                }
            }
            int rl = wm * 64 + i * 16 + tg + 8 * h;
            s_cabs[0][rl][wn * 4 + tq] = a1;
            s_csig[0][rl][wn * 4 + tq] = s1;
            s_cabs[1][rl][wn * 4 + tq] = a2;
            s_csig[1][rl][wn * 4 + tq] = s2;
        }
    }
    __syncthreads();

    // ---- per-row merge 32 -> top-4, write candidates ----
    if (tid < GM) {
        float A_[4] = {-1.f, -1.f, -1.f, -1.f};
        int   S_[4] = {0, 0, 0, 0};
        #pragma unroll
        for (int t = 0; t < 16; ++t) {
            #pragma unroll
            for (int slot = 0; slot < 2; ++slot) {
                float a = s_cabs[slot][tid][t];
                int sg = s_csig[slot][tid][t];
                if (a > A_[3]) {
                    if (a > A_[0]) {
                        A_[3]=A_[2]; S_[3]=S_[2]; A_[2]=A_[1]; S_[2]=S_[1];
                        A_[1]=A_[0]; S_[1]=S_[0]; A_[0]=a; S_[0]=sg;
                    } else if (a > A_[1]) {
                        A_[3]=A_[2]; S_[3]=S_[2]; A_[2]=A_[1]; S_[2]=S_[1];
                        A_[1]=a; S_[1]=sg;
                    } else if (a > A_[2]) {
                        A_[3]=A_[2]; S_[3]=S_[2]; A_[2]=a; S_[2]=sg;
                    } else {
                        A_[3]=a; S_[3]=sg;
                    }
                }
            }
        }
        #pragma unroll
        for (int s = 0; s < 4; ++s) {
            g_pA[(cb * 4 + s) * BROWS + rowbase + tid] = A_[s];
            g_pS[(cb * 4 + s) * BROWS + rowbase + tid] = S_[s];
        }
    }
}

// ---------------- merge + exact fp32 rescore of top-4 + residual update ----------------
__global__ __launch_bounds__(256)
void lex_update(const float* __restrict__ targets, const float* __restrict__ codebook,
                float* __restrict__ out, int step, float decay) {
    __shared__ int   s_k[4][64];
    __shared__ int   s_act[64];
    __shared__ float s_coef[64];
    __shared__ int   s_kidx[64];
    const int tid = threadIdx.x;
    const int rowbase = blockIdx.x * 64;
    const float* src = (step == 0) ? targets : g_resid;

    // phase 1: merge 64 tensor candidates -> global top-4 per row
    if (tid < 64) {
        int row = rowbase + tid;
        float A_[4] = {-1.f, -1.f, -1.f, -1.f};
        int   K_[4] = {0, 0, 0, 0};
        #pragma unroll
        for (int cbi = 0; cbi < NCB; ++cbi) {
            #pragma unroll
            for (int slot = 0; slot < 4; ++slot) {
                float a = g_pA[(cbi * 4 + slot) * BROWS + row];
                int sg = g_pS[(cbi * 4 + slot) * BROWS + row];
                int k = (sg >= 0) ? sg : (-sg - 1);
                if (a > A_[3]) {
                    if (a > A_[0]) {
                        A_[3]=A_[2]; K_[3]=K_[2]; A_[2]=A_[1]; K_[2]=K_[1];
                        A_[1]=A_[0]; K_[1]=K_[0]; A_[0]=a; K_[0]=k;
                    } else if (a > A_[1]) {
                        A_[3]=A_[2]; K_[3]=K_[2]; A_[2]=A_[1]; K_[2]=K_[1];
                        A_[1]=a; K_[1]=k;
                    } else if (a > A_[2]) {
                        A_[3]=A_[2]; K_[3]=K_[2]; A_[2]=a; K_[2]=k;
                    } else {
                        A_[3]=a; K_[3]=k;
                    }
                }
            }
        }
        #pragma unroll
        for (int s = 0; s < 4; ++s) s_k[s][tid] = K_[s];
        s_act[tid] = (g_rnorm[row] >= 0.01f) && (g_tnorm[row] >= 1e-8f);
    }
    __syncthreads();

    // phase 2: exact fp32 rescore of 4 candidates
    const int m = tid >> 2, q = tid & 3;
    const int row = rowbase + m;
    const int k0 = s_k[0][m], k1 = s_k[1][m], k2 = s_k[2][m], k3 = s_k[3][m];
    {
        const float* rp = src + (size_t)row * DDIM + q * 128;
        const float* c0 = codebook + (size_t)k0 * DDIM + q * 128;
        const float* c1 = codebook + (size_t)k1 * DDIM + q * 128;
        const float* c2 = codebook + (size_t)k2 * DDIM + q * 128;
        const float* c3 = codebook + (size_t)k3 * DDIM + q * 128;
        float d0 = 0.f, d1 = 0.f, d2 = 0.f, d3 = 0.f;
        #pragma unroll 4
        for (int i = 0; i < 32; ++i) {
            float4 r4 = *(const float4*)(rp + i * 4);
            float4 v0 = *(const float4*)(c0 + i * 4);
            float4 v1 = *(const float4*)(c1 + i * 4);
            float4 v2 = *(const float4*)(c2 + i * 4);
            float4 v3 = *(const float4*)(c3 + i * 4);
            d0 += r4.x * v0.x + r4.y * v0.y + r4.z * v0.z + r4.w * v0.w;
            d1 += r4.x * v1.x + r4.y * v1.y + r4.z * v1.z + r4.w * v1.w;
            d2 += r4.x * v2.x + r4.y * v2.y + r4.z * v2.z + r4.w * v2.w;
            d3 += r4.x * v3.x + r4.y * v3.y + r4.z * v3.z + r4.w * v3.w;
        }
        d0 += __shfl_xor_sync(0xffffffffu, d0, 1); d0 += __shfl_xor_sync(0xffffffffu, d0, 2);
        d1 += __shfl_xor_sync(0xffffffffu, d1, 1); d1 += __shfl_xor_sync(0xffffffffu, d1, 2);
        d2 += __shfl_xor_sync(0xffffffffu, d2, 1); d2 += __shfl_xor_sync(0xffffffffu, d2, 2);
        d3 += __shfl_xor_sync(0xffffffffu, d3, 1); d3 += __shfl_xor_sync(0xffffffffu, d3, 2);
        if (q == 0) {
            float bD = d0; int bK = k0; float bA = fabsf(d0);
            float a1 = fabsf(d1);
            if (a1 > bA || (a1 == bA && k1 < bK)) { bA = a1; bD = d1; bK = k1; }
            float a2 = fabsf(d2);
            if (a2 > bA || (a2 == bA && k2 < bK)) { bA = a2; bD = d2; bK = k2; }
            float a3 = fabsf(d3);
            if (a3 > bA || (a3 == bA && k3 < bK)) { bA = a3; bD = d3; bK = k3; }
            int bS = (bD >= 0.f) ? bK : -(bK + 1);
            bool active = s_act[m];
            s_coef[m] = active ? ((bD >= 0.f) ? decay : -decay) : 0.f;
            s_kidx[m] = bK;
            out[(size_t)row * LSTEPS + step] = active ? (float)bS : 0.f;
            out[(size_t)BROWS * LSTEPS + (size_t)row * LSTEPS + step] = active ? 1.f : 0.f;
        }
    }
    __syncthreads();

    // phase 3: residual update + bf16 re-split + rnorm
    const bool last = (step == LSTEPS - 1);
    float* resout = out + 2 * (size_t)BROWS * LSTEPS;
    const float coef = s_coef[m];
    const int kk = s_kidx[m];
    const size_t base = (size_t)row * DDIM + q * 128;
    const size_t cbo = (size_t)kk * DDIM + q * 128;
    __nv_bfloat16* dst = g_Abf + (size_t)row * 1024 + q * 128;
    float sum = 0.f;
    #pragma unroll 8
    for (int i = 0; i < 32; ++i) {
        float4 r4 = *(const float4*)(src + base + i * 4);
        float4 c4 = *(const float4*)(codebook + cbo + i * 4);
        float4 o;
        o.x = r4.x - coef * c4.x;
        o.y = r4.y - coef * c4.y;
        o.z = r4.z - coef * c4.z;
        o.w = r4.w - coef * c4.w;
        sum += o.x * o.x + o.y * o.y + o.z * o.z + o.w * o.w;
        *(float4*)(g_resid + base + i * 4) = o;
        split_bf(o.x, dst[i * 4 + 0], dst[512 + i * 4 + 0]);
        split_bf(o.y, dst[i * 4 + 1], dst[512 + i * 4 + 1]);
        split_bf(o.z, dst[i * 4 + 2], dst[512 + i * 4 + 2]);
        split_bf(o.w, dst[i * 4 + 3], dst[512 + i * 4 + 3]);
        if (last) *(float4*)(resout + base + i * 4) = o;
    }
    sum += __shfl_xor_sync(0xffffffffu, sum, 1);
    sum += __shfl_xor_sync(0xffffffffu, sum, 2);
    if (q == 0) g_rnorm[row] = sqrtf(sum);
}

extern "C" void kernel_launch(void* const* d_in, const int* in_sizes, int n_in,
                              void* d_out, int out_size) {
    (void)n_in; (void)out_size;
    const float* targets;
    const float* codebook;
    if (in_sizes[0] == BROWS * DDIM) {
        targets  = (const float*)d_in[0];
        codebook = (const float*)d_in[1];
    } else {
        targets  = (const float*)d_in[1];
        codebook = (const float*)d_in[0];
    }
    cudaFuncSetAttribute(lex_gemm, cudaFuncAttributeMaxDynamicSharedMemorySize, SMEM_DYN);
    float* out = (float*)d_out;

    lex_prep<<<192, 256>>>(targets, codebook);
    for (int s = 0; s < LSTEPS; ++s) {
        float decay = powf(0.95f, (float)(s + 1));
        lex_gemm<<<(BROWS / GM) * NCB, GTHREADS, SMEM_DYN>>>();
        lex_update<<<BROWS / 64, 256>>>(targets, codebook, out, s, decay);
    }
}

// round 7
// speedup vs baseline: 2.7561x; 1.1611x over previous
#include <cuda_runtime.h>
#include <cuda_bf16.h>
#include <math.h>
#include <stdint.h>

#define BROWS 8192
#define DDIM  512
#define KDIM  4096
#define LSTEPS 16

#define GM 128
#define GN 256
#define NCB (KDIM / GN)        // 16 column blocks
#define NCHUNKS 16             // 16 d-chunks of 32 (hi+lo staged together)
#define GTHREADS 512
#define STAGES 3

#define ROWB 144                           // 128B data (64 hi + 64 lo) + 16 pad
#define ABYTES (GM * ROWB)                 // 18432
#define BBYTES (GN * ROWB)                 // 36864
#define STAGEB (ABYTES + BBYTES)           // 55296
#define SMEM_DYN (STAGES * STAGEB)         // 165888

// ---------------- device state ----------------
__device__ __align__(128) float g_resid[BROWS * DDIM];
__device__ __align__(128) __nv_bfloat16 g_Abf[BROWS * 1024];  // [row][0:512)=hi,[512:1024)=lo
__device__ __align__(128) __nv_bfloat16 g_Bbf[KDIM * 1024];
__device__ float g_rnorm[BROWS];
__device__ float g_tnorm[BROWS];
__device__ float g_pA[4 * NCB * BROWS];
__device__ int   g_pS[4 * NCB * BROWS];

// ---------------- helpers ----------------
__device__ __forceinline__ uint32_t smem_u32(const void* p) {
    uint32_t a;
    asm("{ .reg .u64 t; cvta.to.shared.u64 t, %1; cvt.u32.u64 %0, t; }" : "=r"(a) : "l"(p));
    return a;
}
__device__ __forceinline__ void cpasync16(uint32_t dst, const void* src) {
    asm volatile("cp.async.cg.shared.global [%0], [%1], 16;" :: "r"(dst), "l"(src));
}
#define CP_COMMIT() asm volatile("cp.async.commit_group;" ::: "memory")

__device__ __forceinline__ void mma_bf16(float* d, const uint32_t* a, const uint32_t* b) {
    asm volatile(
        "mma.sync.aligned.m16n8k16.row.col.f32.bf16.bf16.f32 "
        "{%0,%1,%2,%3}, {%4,%5,%6,%7}, {%8,%9}, {%0,%1,%2,%3};"
        : "+f"(d[0]), "+f"(d[1]), "+f"(d[2]), "+f"(d[3])
        : "r"(a[0]), "r"(a[1]), "r"(a[2]), "r"(a[3]), "r"(b[0]), "r"(b[1]));
}

__device__ __forceinline__ void split_bf(float v, __nv_bfloat16& h, __nv_bfloat16& l) {
    h = __float2bfloat16(v);
    l = __float2bfloat16(v - __bfloat162float(h));
}

// ---------------- prep: split inputs into bf16 hi/lo, norms ----------------
__global__ __launch_bounds__(256)
void lex_prep(const float* __restrict__ targets, const float* __restrict__ codebook) {
    const int tid = threadIdx.x;
    const int m = tid >> 2, q = tid & 3;
    if (blockIdx.x < 128) {
        int row = blockIdx.x * 64 + m;
        const float* src = targets + (size_t)row * DDIM + q * 128;
        __nv_bfloat16* dst = g_Abf + (size_t)row * 1024 + q * 128;
        float sum = 0.f;
        #pragma unroll 8
        for (int i = 0; i < 128; ++i) {
            float v = src[i];
            sum += v * v;
            split_bf(v, dst[i], dst[512 + i]);
        }
        sum += __shfl_xor_sync(0xffffffffu, sum, 1);
        sum += __shfl_xor_sync(0xffffffffu, sum, 2);
        if (q == 0) { float n = sqrtf(sum); g_rnorm[row] = n; g_tnorm[row] = n; }
    } else {
        int row = (blockIdx.x - 128) * 64 + m;
        const float* src = codebook + (size_t)row * DDIM + q * 128;
        __nv_bfloat16* dst = g_Bbf + (size_t)row * 1024 + q * 128;
        #pragma unroll 8
        for (int i = 0; i < 128; ++i) {
            split_bf(src[i], dst[i], dst[512 + i]);
        }
    }
}

// ---------------- GEMM (bf16 triple, fused hi/lo chunks) + top-4 ----------------
__global__ __launch_bounds__(GTHREADS, 1)
void lex_gemm() {
    extern __shared__ char dsm[];
    __shared__ float s_cabs[2][GM][17];
    __shared__ int   s_csig[2][GM][17];

    const int tid = threadIdx.x;
    const int wid = tid >> 5;      // 0..15
    const int lane = tid & 31;
    const int tg = lane >> 2;      // 0..7
    const int tq = lane & 3;       // 0..3
    const int wm = wid >> 2;       // 0..3  (32-row group)
    const int wn = wid & 3;        // 0..3  (64-col group)
    const int rowblock = blockIdx.x >> 4;
    const int cb = blockIdx.x & 15;
    const int rowbase = rowblock * GM;
    const int colbase = cb * GN;
    const uint32_t sbase = smem_u32(dsm);

    // stage chunk c: A/B rows, both hi (seg 0) and lo (seg 1) 32-d slices
    auto issue = [&](int c) {
        const int dbase = c * 32;
        const uint32_t base = sbase + (uint32_t)(c % STAGES) * STAGEB;
        #pragma unroll
        for (int i = 0; i < 2; ++i) {
            int idx = tid + i * GTHREADS;     // 0..1023
            int r = idx >> 3;
            int seg = (idx >> 2) & 1, c16 = idx & 3;
            cpasync16(base + (uint32_t)(r * ROWB + seg * 64 + c16 * 16),
                      g_Abf + (size_t)(rowbase + r) * 1024 + seg * 512 + dbase + c16 * 8);
        }
        #pragma unroll
        for (int i = 0; i < 4; ++i) {
            int idx = tid + i * GTHREADS;     // 0..2047
            int n = idx >> 3;
            int seg = (idx >> 2) & 1, c16 = idx & 3;
            cpasync16(base + ABYTES + (uint32_t)(n * ROWB + seg * 64 + c16 * 16),
                      g_Bbf + (size_t)(colbase + n) * 1024 + seg * 512 + dbase + c16 * 8);
        }
        CP_COMMIT();
    };

    float acc[2][8][4];
    #pragma unroll
    for (int i = 0; i < 2; ++i)
        #pragma unroll
        for (int j = 0; j < 8; ++j)
            #pragma unroll
            for (int r = 0; r < 4; ++r) acc[i][j][r] = 0.f;

    issue(0); issue(1);

    for (int c = 0; c < NCHUNKS; ++c) {
        asm volatile("cp.async.wait_group 1;" ::: "memory");
        __syncthreads();
        if (c + 2 < NCHUNKS) issue(c + 2);
        else CP_COMMIT();                       // keep group accounting uniform

        const char* As = dsm + (size_t)(c % STAGES) * STAGEB;
        const char* Bs = As + ABYTES;

        #pragma unroll
        for (int ks = 0; ks < 2; ++ks) {
            const int koff = ks * 32;           // 16 bf16 = 32 bytes within 64B seg
            uint32_t ah[2][4], al[2][4];
            #pragma unroll
            for (int i = 0; i < 2; ++i) {
                const char* p = As + (wm * 32 + i * 16 + tg) * ROWB + koff + tq * 4;
                ah[i][0] = *(const uint32_t*)(p);
                ah[i][1] = *(const uint32_t*)(p + 8 * ROWB);
                ah[i][2] = *(const uint32_t*)(p + 16);
                ah[i][3] = *(const uint32_t*)(p + 8 * ROWB + 16);
                al[i][0] = *(const uint32_t*)(p + 64);
                al[i][1] = *(const uint32_t*)(p + 8 * ROWB + 64);
                al[i][2] = *(const uint32_t*)(p + 80);
                al[i][3] = *(const uint32_t*)(p + 8 * ROWB + 80);
            }
            uint32_t bh[8][2], bl[8][2];
            #pragma unroll
            for (int j = 0; j < 8; ++j) {
                const char* p = Bs + (wn * 64 + j * 8 + tg) * ROWB + koff + tq * 4;
                bh[j][0] = *(const uint32_t*)(p);
                bh[j][1] = *(const uint32_t*)(p + 16);
                bl[j][0] = *(const uint32_t*)(p + 64);
                bl[j][1] = *(const uint32_t*)(p + 80);
            }
            #pragma unroll
            for (int i = 0; i < 2; ++i)
                #pragma unroll
                for (int j = 0; j < 8; ++j) {
                    mma_bf16(acc[i][j], ah[i], bh[j]);   // hi*hi
                    mma_bf16(acc[i][j], al[i], bh[j]);   // lo*hi
                    mma_bf16(acc[i][j], ah[i], bl[j]);   // hi*lo
                }
        }
    }

    // ---- per-thread top-2 candidates per row-slot ----
    #pragma unroll
    for (int i = 0; i < 2; ++i) {
        #pragma unroll
        for (int h = 0; h < 2; ++h) {
            float a1 = -1.f, a2 = -1.f;
            int s1 = 0, s2 = 0;
            #pragma unroll
            for (int j = 0; j < 8; ++j) {
                #pragma unroll
                for (int cc = 0; cc < 2; ++cc) {
                    float v = acc[i][j][h * 2 + cc];
                    float a = fabsf(v);
                    int k = colbase + wn * 64 + j * 8 + tq * 2 + cc;
                    int sg = (v >= 0.f) ? k : -(k + 1);
                    if (a > a1) { a2 = a1; s2 = s1; a1 = a; s1 = sg; }
                    else if (a > a2) { a2 = a; s2 = sg; }
                }
            }
            int rl = wm * 32 + i * 16 + tg + 8 * h;
            s_cabs[0][rl][wn * 4 + tq] = a1;
            s_csig[0][rl][wn * 4 + tq] = s1;
            s_cabs[1][rl][wn * 4 + tq] = a2;
            s_csig[1][rl][wn * 4 + tq] = s2;
        }
    }
    __syncthreads();

    // ---- per-row merge 32 -> top-4, write candidates ----
    if (tid < GM) {
        float A_[4] = {-1.f, -1.f, -1.f, -1.f};
        int   S_[4] = {0, 0, 0, 0};
        #pragma unroll
        for (int t = 0; t < 16; ++t) {
            #pragma unroll
            for (int slot = 0; slot < 2; ++slot) {
                float a = s_cabs[slot][tid][t];
                int sg = s_csig[slot][tid][t];
                if (a > A_[3]) {
                    if (a > A_[0]) {
                        A_[3]=A_[2]; S_[3]=S_[2]; A_[2]=A_[1]; S_[2]=S_[1];
                        A_[1]=A_[0]; S_[1]=S_[0]; A_[0]=a; S_[0]=sg;
                    } else if (a > A_[1]) {
                        A_[3]=A_[2]; S_[3]=S_[2]; A_[2]=A_[1]; S_[2]=S_[1];
                        A_[1]=a; S_[1]=sg;
                    } else if (a > A_[2]) {
                        A_[3]=A_[2]; S_[3]=S_[2]; A_[2]=a; S_[2]=sg;
                    } else {
                        A_[3]=a; S_[3]=sg;
                    }
                }
            }
        }
        #pragma unroll
        for (int s = 0; s < 4; ++s) {
            g_pA[(cb * 4 + s) * BROWS + rowbase + tid] = A_[s];
            g_pS[(cb * 4 + s) * BROWS + rowbase + tid] = S_[s];
        }
    }
}

// ---------------- merge + exact fp32 rescore of top-4 + residual update ----------------
__global__ __launch_bounds__(256)
void lex_update(const float* __restrict__ targets, const float* __restrict__ codebook,
                float* __restrict__ out, int step, float decay) {
    __shared__ int   s_k[4][64];
    __shared__ int   s_act[64];
    __shared__ float s_coef[64];
    __shared__ int   s_kidx[64];
    const int tid = threadIdx.x;
    const int rowbase = blockIdx.x * 64;
    const float* src = (step == 0) ? targets : g_resid;

    if (tid < 64) {
        int row = rowbase + tid;
        float A_[4] = {-1.f, -1.f, -1.f, -1.f};
        int   K_[4] = {0, 0, 0, 0};
        #pragma unroll
        for (int cbi = 0; cbi < NCB; ++cbi) {
            #pragma unroll
            for (int slot = 0; slot < 4; ++slot) {
                float a = g_pA[(cbi * 4 + slot) * BROWS + row];
                int sg = g_pS[(cbi * 4 + slot) * BROWS + row];
                int k = (sg >= 0) ? sg : (-sg - 1);
                if (a > A_[3]) {
                    if (a > A_[0]) {
                        A_[3]=A_[2]; K_[3]=K_[2]; A_[2]=A_[1]; K_[2]=K_[1];
                        A_[1]=A_[0]; K_[1]=K_[0]; A_[0]=a; K_[0]=k;
                    } else if (a > A_[1]) {
                        A_[3]=A_[2]; K_[3]=K_[2]; A_[2]=A_[1]; K_[2]=K_[1];
                        A_[1]=a; K_[1]=k;
                    } else if (a > A_[2]) {
                        A_[3]=A_[2]; K_[3]=K_[2]; A_[2]=a; K_[2]=k;
                    } else {
                        A_[3]=a; K_[3]=k;
                    }
                }
            }
        }
        #pragma unroll
        for (int s = 0; s < 4; ++s) s_k[s][tid] = K_[s];
        s_act[tid] = (g_rnorm[row] >= 0.01f) && (g_tnorm[row] >= 1e-8f);
    }
    __syncthreads();

    const int m = tid >> 2, q = tid & 3;
    const int row = rowbase + m;
    const int k0 = s_k[0][m], k1 = s_k[1][m], k2 = s_k[2][m], k3 = s_k[3][m];
    {
        const float* rp = src + (size_t)row * DDIM + q * 128;
        const float* c0 = codebook + (size_t)k0 * DDIM + q * 128;
        const float* c1 = codebook + (size_t)k1 * DDIM + q * 128;
        const float* c2 = codebook + (size_t)k2 * DDIM + q * 128;
        const float* c3 = codebook + (size_t)k3 * DDIM + q * 128;
        float d0 = 0.f, d1 = 0.f, d2 = 0.f, d3 = 0.f;
        #pragma unroll 4
        for (int i = 0; i < 32; ++i) {
            float4 r4 = *(const float4*)(rp + i * 4);
            float4 v0 = *(const float4*)(c0 + i * 4);
            float4 v1 = *(const float4*)(c1 + i * 4);
            float4 v2 = *(const float4*)(c2 + i * 4);
            float4 v3 = *(const float4*)(c3 + i * 4);
            d0 += r4.x * v0.x + r4.y * v0.y + r4.z * v0.z + r4.w * v0.w;
            d1 += r4.x * v1.x + r4.y * v1.y + r4.z * v1.z + r4.w * v1.w;
            d2 += r4.x * v2.x + r4.y * v2.y + r4.z * v2.z + r4.w * v2.w;
            d3 += r4.x * v3.x + r4.y * v3.y + r4.z * v3.z + r4.w * v3.w;
        }
        d0 += __shfl_xor_sync(0xffffffffu, d0, 1); d0 += __shfl_xor_sync(0xffffffffu, d0, 2);
        d1 += __shfl_xor_sync(0xffffffffu, d1, 1); d1 += __shfl_xor_sync(0xffffffffu, d1, 2);
        d2 += __shfl_xor_sync(0xffffffffu, d2, 1); d2 += __shfl_xor_sync(0xffffffffu, d2, 2);
        d3 += __shfl_xor_sync(0xffffffffu, d3, 1); d3 += __shfl_xor_sync(0xffffffffu, d3, 2);
        if (q == 0) {
            float bD = d0; int bK = k0; float bA = fabsf(d0);
            float a1 = fabsf(d1);
            if (a1 > bA || (a1 == bA && k1 < bK)) { bA = a1; bD = d1; bK = k1; }
            float a2 = fabsf(d2);
            if (a2 > bA || (a2 == bA && k2 < bK)) { bA = a2; bD = d2; bK = k2; }
            float a3 = fabsf(d3);
            if (a3 > bA || (a3 == bA && k3 < bK)) { bA = a3; bD = d3; bK = k3; }
            int bS = (bD >= 0.f) ? bK : -(bK + 1);
            bool active = s_act[m];
            s_coef[m] = active ? ((bD >= 0.f) ? decay : -decay) : 0.f;
            s_kidx[m] = bK;
            out[(size_t)row * LSTEPS + step] = active ? (float)bS : 0.f;
            out[(size_t)BROWS * LSTEPS + (size_t)row * LSTEPS + step] = active ? 1.f : 0.f;
        }
    }
    __syncthreads();

    const bool last = (step == LSTEPS - 1);
    float* resout = out + 2 * (size_t)BROWS * LSTEPS;
    const float coef = s_coef[m];
    const int kk = s_kidx[m];
    const size_t base = (size_t)row * DDIM + q * 128;
    const size_t cbo = (size_t)kk * DDIM + q * 128;
    __nv_bfloat16* dst = g_Abf + (size_t)row * 1024 + q * 128;
    float sum = 0.f;
    #pragma unroll 8
    for (int i = 0; i < 32; ++i) {
        float4 r4 = *(const float4*)(src + base + i * 4);
        float4 c4 = *(const float4*)(codebook + cbo + i * 4);
        float4 o;
        o.x = r4.x - coef * c4.x;
        o.y = r4.y - coef * c4.y;
        o.z = r4.z - coef * c4.z;
        o.w = r4.w - coef * c4.w;
        sum += o.x * o.x + o.y * o.y + o.z * o.z + o.w * o.w;
        *(float4*)(g_resid + base + i * 4) = o;
        split_bf(o.x, dst[i * 4 + 0], dst[512 + i * 4 + 0]);
        split_bf(o.y, dst[i * 4 + 1], dst[512 + i * 4 + 1]);
        split_bf(o.z, dst[i * 4 + 2], dst[512 + i * 4 + 2]);
        split_bf(o.w, dst[i * 4 + 3], dst[512 + i * 4 + 3]);
        if (last) *(float4*)(resout + base + i * 4) = o;
    }
    sum += __shfl_xor_sync(0xffffffffu, sum, 1);
    sum += __shfl_xor_sync(0xffffffffu, sum, 2);
    if (q == 0) g_rnorm[row] = sqrtf(sum);
}

extern "C" void kernel_launch(void* const* d_in, const int* in_sizes, int n_in,
                              void* d_out, int out_size) {
    (void)n_in; (void)out_size;
    const float* targets;
    const float* codebook;
    if (in_sizes[0] == BROWS * DDIM) {
        targets  = (const float*)d_in[0];
        codebook = (const float*)d_in[1];
    } else {
        targets  = (const float*)d_in[1];
        codebook = (const float*)d_in[0];
    }
    cudaFuncSetAttribute(lex_gemm, cudaFuncAttributeMaxDynamicSharedMemorySize, SMEM_DYN);
    float* out = (float*)d_out;

    lex_prep<<<192, 256>>>(targets, codebook);
    for (int s = 0; s < LSTEPS; ++s) {
        float decay = powf(0.95f, (float)(s + 1));
        lex_gemm<<<(BROWS / GM) * NCB, GTHREADS, SMEM_DYN>>>();
        lex_update<<<BROWS / 64, 256>>>(targets, codebook, out, s, decay);
    }
}